// round 17
// baseline (speedup 1.0000x reference)
#include <cuda_runtime.h>
#include <cuda_bf16.h>
#include <cstdint>

// ---------------------------------------------------------------------------
// SimpleLSTM on GB300 (plain sm_103 PTX) — round 17 = r11 +
//   (a) 6 independent HMMA accumulator chains (kt-parity split) to cover
//       tensor-op result latency (was 3 chains, 16-deep serial each);
//   (b) A2 (lo-split W) fragments moved to SMEM (48KB, one LDS.128 per kt)
//       to pay the +12 accumulator registers (net ~-48 regs).
//   Everything else identical to the verified 2975us kernel: tagged-data L2
//   exchange, register A1 fragments, interleaved B fragments, 2 barriers.
// ---------------------------------------------------------------------------

#define NB    128
#define LSEQ  2048
#define HDIM  256
#define EMB   256
#define VOC   32000
#define G3    768
#define NT    256

__device__ float    g_T[VOC * G3];          // token-gate table (~98.3 MB)
__device__ float    g_Hbuf[2][NB * HDIM];   // H double buffer (tagged values)
__device__ uint32_t g_EhG[VOC * 128];       // E hi split, bf16x2 words
__device__ uint32_t g_ElG[VOC * 128];       // E lo split
__device__ uint32_t g_WhG[G3 * 128];        // W_x hi split (live gate rows)
__device__ uint32_t g_WlG[G3 * 128];        // W_x lo split

// ---------------------------------------------------------------------------
// helpers
// ---------------------------------------------------------------------------
__device__ __forceinline__ float4 ldv4_volatile(const float* p)
{
    float4 v;
    asm volatile("ld.volatile.global.v4.f32 {%0, %1, %2, %3}, [%4];"
                 : "=f"(v.x), "=f"(v.y), "=f"(v.z), "=f"(v.w) : "l"(p)
                 : "memory");
    return v;
}

__device__ __forceinline__ float sig_fast(float x)
{
    return __fdividef(1.0f, 1.0f + __expf(-x));
}

__device__ __forceinline__ float tanh_fast(float x)
{
    return __fdividef(2.0f, 1.0f + __expf(-2.0f * x)) - 1.0f;
}

// split a float2 (consecutive k pair) into bf16x2 hi and lo b32 values.
__device__ __forceinline__ void split2(float2 f, uint32_t& hi, uint32_t& lo)
{
    __nv_bfloat16 h0 = __float2bfloat16_rn(f.x);
    __nv_bfloat16 h1 = __float2bfloat16_rn(f.y);
    __nv_bfloat16 l0 = __float2bfloat16_rn(f.x - __bfloat162float(h0));
    __nv_bfloat16 l1 = __float2bfloat16_rn(f.y - __bfloat162float(h1));
    __nv_bfloat162 ph = __halves2bfloat162(h0, h1);
    __nv_bfloat162 pl = __halves2bfloat162(l0, l1);
    hi = *(uint32_t*)&ph;
    lo = *(uint32_t*)&pl;
}

__device__ __forceinline__ void mma16816(float& c0, float& c1, float& c2, float& c3,
                                         uint32_t a0, uint32_t a1, uint32_t a2, uint32_t a3,
                                         uint32_t b0, uint32_t b1)
{
    asm volatile(
        "mma.sync.aligned.m16n8k16.row.col.f32.bf16.bf16.f32 "
        "{%0,%1,%2,%3}, {%4,%5,%6,%7}, {%8,%9}, {%0,%1,%2,%3};"
        : "+f"(c0), "+f"(c1), "+f"(c2), "+f"(c3)
        : "r"(a0), "r"(a1), "r"(a2), "r"(a3), "r"(b0), "r"(b1));
}

__device__ __forceinline__ int grow_of(int g)   // live-gate row -> W row
{
    int gate = g >> 8, jj = g & 255;
    return (gate == 0 ? 0 : (gate == 1 ? 512 : 768)) + jj;
}

// ---------------------------------------------------------------------------
// Kernel 0: split E and W_x (input half, live gate rows) into bf16 hi/lo.
// ---------------------------------------------------------------------------
__global__ void split_kernel(const float* __restrict__ E,
                             const float* __restrict__ Ww)
{
    int idx = blockIdx.x * 256 + threadIdx.x;
    uint32_t h0, l0, h1, l1;
    if (idx < VOC * 64) {
        int row = idx >> 6, f4 = idx & 63;
        float4 e = *(const float4*)(E + row * EMB + f4 * 4);
        split2(make_float2(e.x, e.y), h0, l0);
        split2(make_float2(e.z, e.w), h1, l1);
        *(uint2*)&g_EhG[row * 128 + f4 * 2] = make_uint2(h0, h1);
        *(uint2*)&g_ElG[row * 128 + f4 * 2] = make_uint2(l0, l1);
    } else {
        int widx = idx - VOC * 64;
        int row = widx >> 6, f4 = widx & 63;      // row = live gate idx 0..767
        int grow = grow_of(row);
        float4 w = *(const float4*)(Ww + grow * 512 + 256 + f4 * 4);
        split2(make_float2(w.x, w.y), h0, l0);
        split2(make_float2(w.z, w.w), h1, l1);
        *(uint2*)&g_WhG[row * 128 + f4 * 2] = make_uint2(h0, h1);
        *(uint2*)&g_WlG[row * 128 + f4 * 2] = make_uint2(l0, l1);
    }
}

// ---------------------------------------------------------------------------
// Kernel 1: token table GEMM via HMMA (M=32000, N=768, K=256), 64x64 tiles.
//   3-term bf16 split: EhWh + EhWl + ElWh. SMEM row stride 36 words.
// ---------------------------------------------------------------------------
__global__ void __launch_bounds__(256)
table_kernel(const float* __restrict__ Wb)
{
    __shared__ uint32_t Eh[64 * 36], El[64 * 36];
    __shared__ uint32_t Wh[64 * 36], Wl[64 * 36];

    const int tid  = threadIdx.x;
    const int v0   = blockIdx.x * 64;
    const int g0   = blockIdx.y * 64;
    const int wid  = tid >> 5, lane = tid & 31;
    const int gid  = lane >> 2, tig = lane & 3;
    const int m0   = (wid & 3) * 16;
    const int n0   = (wid >> 2) * 32;

    float acc[4][4];
#pragma unroll
    for (int i = 0; i < 4; i++)
#pragma unroll
        for (int j = 0; j < 4; j++) acc[i][j] = 0.0f;

    for (int c = 0; c < 4; c++) {          // K chunk of 64
#pragma unroll
        for (int it = 0; it < 8; it++) {
            int idx = tid + it * 256;       // 0..2047
            int buf = idx >> 9, rem = idx & 511;
            int row = rem >> 3, w4 = rem & 7;
            const uint32_t* src;
            uint32_t* dst;
            if (buf == 0)      { src = &g_EhG[(v0 + row) * 128]; dst = Eh; }
            else if (buf == 1) { src = &g_ElG[(v0 + row) * 128]; dst = El; }
            else if (buf == 2) { src = &g_WhG[(g0 + row) * 128]; dst = Wh; }
            else               { src = &g_WlG[(g0 + row) * 128]; dst = Wl; }
            uint4 v = *(const uint4*)(src + c * 32 + w4 * 4);
            *(uint4*)(dst + row * 36 + w4 * 4) = v;
        }
        __syncthreads();

#pragma unroll
        for (int ktL = 0; ktL < 4; ktL++) {
            int kw = ktL * 8 + tig;
            uint32_t ah0 = Eh[(m0 + gid) * 36 + kw];
            uint32_t ah1 = Eh[(m0 + gid + 8) * 36 + kw];
            uint32_t ah2 = Eh[(m0 + gid) * 36 + kw + 4];
            uint32_t ah3 = Eh[(m0 + gid + 8) * 36 + kw + 4];
            uint32_t al0 = El[(m0 + gid) * 36 + kw];
            uint32_t al1 = El[(m0 + gid + 8) * 36 + kw];
            uint32_t al2 = El[(m0 + gid) * 36 + kw + 4];
            uint32_t al3 = El[(m0 + gid + 8) * 36 + kw + 4];
#pragma unroll
            for (int nn = 0; nn < 4; nn++) {
                int wr = (n0 + nn * 8 + gid) * 36 + kw;
                uint32_t bh0 = Wh[wr], bh1 = Wh[wr + 4];
                uint32_t bl0 = Wl[wr], bl1 = Wl[wr + 4];
                mma16816(acc[nn][0], acc[nn][1], acc[nn][2], acc[nn][3],
                         ah0, ah1, ah2, ah3, bh0, bh1);
                mma16816(acc[nn][0], acc[nn][1], acc[nn][2], acc[nn][3],
                         ah0, ah1, ah2, ah3, bl0, bl1);
                mma16816(acc[nn][0], acc[nn][1], acc[nn][2], acc[nn][3],
                         al0, al1, al2, al3, bh0, bh1);
            }
        }
        __syncthreads();
    }

#pragma unroll
    for (int nn = 0; nn < 4; nn++) {
        int g  = g0 + n0 + nn * 8 + tig * 2;
        float b0 = Wb[grow_of(g)];
        float b1 = Wb[grow_of(g + 1)];
        int vA = v0 + m0 + gid, vB = vA + 8;
        *(float2*)&g_T[vA * G3 + g] = make_float2(acc[nn][0] + b0, acc[nn][1] + b1);
        *(float2*)&g_T[vB * G3 + g] = make_float2(acc[nn][2] + b0, acc[nn][3] + b1);
    }
}

// ---------------------------------------------------------------------------
// Kernel 2: persistent recurrence, HMMA + tagged exchange (2 syncs/step).
//   A1 fragments in registers; A2 fragments in SMEM; 6 accumulator chains.
// ---------------------------------------------------------------------------

#define KTW 132   // words per k-tile slot (128 + 4 pad)

// dynamic SMEM layout (bytes)
#define SM_BF   0                     // uint32 Bf[16*KTW]      : 8448
#define SM_GS   8448                  // float  Gsm2[96*9]      : 3456
#define SM_CS   11904                 // float  Csm[256]        : 1024
#define SM_TOK  12928                 // int    tokb[16]        : 64, pad 128
#define SM_A2   13056                 // uint4  Asm2[6*16*32]   : 49152
#define SMEM_TOTAL 62208

__global__ void __launch_bounds__(NT, 1)
lstm_kernel(const void* __restrict__ Xraw,
            const float* __restrict__ Ww,
            float* __restrict__ out)
{
    extern __shared__ char smem[];
    uint32_t* Bf   = (uint32_t*)(smem + SM_BF);
    float*    Gsm2 = (float*)(smem + SM_GS);
    float*    Csm  = (float*)(smem + SM_CS);
    int*      tokb = (int*)(smem + SM_TOK);
    uint4*    Asm2 = (uint4*)(smem + SM_A2);

    const int tid  = threadIdx.x;
    const int wid  = tid >> 5;
    const int lane = tid & 31;
    const int bt   = blockIdx.x >> 3;
    const int ct   = blockIdx.x & 7;
    const int rb   = bt * 8;
    const int j0   = ct * 32;

    const int gid = lane >> 2;      // mma group id
    const int tig = lane & 3;       // mma thread-in-group

    // --- int64 vs int32 token buffer detection ----------------------------
    const int* Xi = (const int*)Xraw;
    bool is64 = true;
#pragma unroll
    for (int i = 0; i < 16; i++)
        if (Xi[2 * i + 1] != 0) is64 = false;
    const long long* Xl = (const long long*)Xraw;

    // --- init: zero Bf, C; first tokens ------------------------------------
    for (int i = tid; i < 16 * KTW; i += NT) Bf[i] = 0u;
    Csm[tid] = 0.0f;
    if (tid < 8)
        tokb[tid] = is64 ? (int)Xl[(rb + tid) * LSEQ] : Xi[(rb + tid) * LSEQ];

    // --- build W fragments: A1 (hi) in registers, A2 (lo) in SMEM -----------
    uint32_t A1[16][4];
    if (wid < 6) {
        int m0 = wid * 16 + gid, m1 = m0 + 8;
        int ga = m0 >> 5, ja = m0 & 31;
        int gb = m1 >> 5, jb = m1 & 31;
        int grow0 = (ga == 0 ? 0 : (ga == 1 ? 512 : 768)) + j0 + ja;
        int grow1 = (gb == 0 ? 0 : (gb == 1 ? 512 : 768)) + j0 + jb;
#pragma unroll
        for (int kt = 0; kt < 16; kt++) {
            int k = kt * 16 + tig * 2;
            float2 f;
            uint32_t l0, l1, l2, l3;
            f = __ldg((const float2*)(Ww + grow0 * 512 + k));
            split2(f, A1[kt][0], l0);
            f = __ldg((const float2*)(Ww + grow1 * 512 + k));
            split2(f, A1[kt][1], l1);
            f = __ldg((const float2*)(Ww + grow0 * 512 + k + 8));
            split2(f, A1[kt][2], l2);
            f = __ldg((const float2*)(Ww + grow1 * 512 + k + 8));
            split2(f, A1[kt][3], l3);
            Asm2[(wid * 16 + kt) * 32 + lane] = make_uint4(l0, l1, l2, l3);
        }
    }
    __syncthreads();

    // --- fill mapping (all 8 warps; producer rank = wid) --------------------
    const int kq = wid;
    const int fq = lane & 7;            // k-quad within slice
    const int r0 = lane >> 3;           // batch rows 0..3 (v0)
    const int r1 = r0 + 4;              // batch rows 4..7 (v1)
    const int fkt  = kq * 2 + (fq >> 2);
    const int freg = (fq >> 1) & 1;
    const int ftig = (fq & 1) * 2;
    uint2* B2 = (uint2*)Bf;
    const int u0a = fkt * (KTW / 2) + (r0 * 4 + ftig) * 2 + freg;
    const int u0b = fkt * (KTW / 2) + (r0 * 4 + ftig + 1) * 2 + freg;
    const int u1a = fkt * (KTW / 2) + (r1 * 4 + ftig) * 2 + freg;
    const int u1b = fkt * (KTW / 2) + (r1 * 4 + ftig + 1) * 2 + freg;

    const int er = tid >> 5, ej = lane;  // epilogue element (row, col)

    for (int t = 0; t < LSEQ; t++) {
        const int cur = t & 1, nxt = cur ^ 1;

        // ---- Gx prefetch (token-determined; overlaps the poll) ------------
        const float* Tr = g_T + (long long)tokb[cur * 8 + er] * G3 + j0 + ej;
        float gxF = __ldg(Tr);
        float gxO = __ldg(Tr + 256);
        float gxH = __ldg(Tr + 512);

        if (tid < 8 && t + 1 < LSEQ)
            tokb[nxt * 8 + tid] = is64 ? (int)Xl[(rb + tid) * LSEQ + t + 1]
                                       : Xi[(rb + tid) * LSEQ + t + 1];

        // ---- fill: poll tagged H slice (self included), emit B fragments --
        if (t > 0) {
            const float cr = 4.0f + 8.0f * (float)(((t - 1) >> 1) & 3);
            const float* hb = g_Hbuf[cur];
            const float* p0 = hb + (rb + r0) * HDIM + kq * 32 + fq * 4;
            const float* p1 = hb + (rb + r1) * HDIM + kq * 32 + fq * 4;
            float4 v0, v1;
            bool d0 = false, d1 = false;
            do {
                if (!d0) { v0 = ldv4_volatile(p0); d0 = fabsf(v0.x - cr) < 2.0f; }
                if (!d1) { v1 = ldv4_volatile(p1); d1 = fabsf(v1.x - cr) < 2.0f; }
            } while (!(d0 && d1));
            v0.x -= cr; v0.y -= cr; v0.z -= cr; v0.w -= cr;
            v1.x -= cr; v1.y -= cr; v1.z -= cr; v1.w -= cr;
            uint32_t h0, l0, h1, l1;
            split2(make_float2(v0.x, v0.y), h0, l0);
            split2(make_float2(v0.z, v0.w), h1, l1);
            B2[u0a] = make_uint2(h0, l0);
            B2[u0b] = make_uint2(h1, l1);
            split2(make_float2(v1.x, v1.y), h0, l0);
            split2(make_float2(v1.z, v1.w), h1, l1);
            B2[u1a] = make_uint2(h0, l0);
            B2[u1b] = make_uint2(h1, l1);
        }
        __syncthreads();   // (1) B fragments ready

        // ---- HMMA: warps 0..5, 16 k-tiles x 3 terms, 6 accumulator chains --
        if (wid < 6) {
            float aA[2][4], aB[2][4], aC[2][4];
#pragma unroll
            for (int p = 0; p < 2; p++)
#pragma unroll
                for (int q = 0; q < 4; q++) {
                    aA[p][q] = 0.f; aB[p][q] = 0.f; aC[p][q] = 0.f;
                }
#pragma unroll
            for (int kt = 0; kt < 16; kt++) {
                const int p = kt & 1;
                uint4 b  = *(const uint4*)&Bf[kt * KTW + lane * 4];
                uint4 a2 = Asm2[(wid * 16 + kt) * 32 + lane];
                // words: x=b1r0(hi), y=b2r0(lo), z=b1r1(hi), w=b2r1(lo)
                mma16816(aA[p][0], aA[p][1], aA[p][2], aA[p][3],
                         A1[kt][0], A1[kt][1], A1[kt][2], A1[kt][3], b.x, b.z);
                mma16816(aB[p][0], aB[p][1], aB[p][2], aB[p][3],
                         A1[kt][0], A1[kt][1], A1[kt][2], A1[kt][3], b.y, b.w);
                mma16816(aC[p][0], aC[p][1], aC[p][2], aC[p][3],
                         a2.x, a2.y, a2.z, a2.w, b.x, b.z);
            }
            int m0 = wid * 16 + gid, m1 = m0 + 8;
            Gsm2[m0 * 9 + tig * 2] =
                (aA[0][0] + aA[1][0]) + (aB[0][0] + aB[1][0]) + (aC[0][0] + aC[1][0]);
            Gsm2[m0 * 9 + tig * 2 + 1] =
                (aA[0][1] + aA[1][1]) + (aB[0][1] + aB[1][1]) + (aC[0][1] + aC[1][1]);
            Gsm2[m1 * 9 + tig * 2] =
                (aA[0][2] + aA[1][2]) + (aB[0][2] + aB[1][2]) + (aC[0][2] + aC[1][2]);
            Gsm2[m1 * 9 + tig * 2 + 1] =
                (aA[0][3] + aA[1][3]) + (aB[0][3] + aB[1][3]) + (aC[0][3] + aC[1][3]);
        }
        __syncthreads();   // (2) G ready

        // ---- epilogue: gates, C, H_new (tagged store) ------------------------
        {
            const float cw = 4.0f + 8.0f * (float)((t >> 1) & 3);
            float gF = gxF + Gsm2[ej * 9 + er];
            float gO = gxO + Gsm2[(32 + ej) * 9 + er];
            float gH = gxH + Gsm2[(64 + ej) * 9 + er];
            float F  = sig_fast(gF);
            float O  = sig_fast(gO);
            float Ht = tanh_fast(gH);
            float c  = F * Csm[tid] + O * Ht;      // faithful: uses O, not I
            Csm[tid] = c;
            float hn = O * tanh_fast(c);
            __stcg(g_Hbuf[nxt] + (rb + er) * HDIM + j0 + ej, hn + cw);
            if (t == LSEQ - 1)
                out[(rb + er) * HDIM + j0 + ej] = hn;
        }
        // no third sync: Bf next write fenced by (2); Gsm2 next write by (1)
    }
}

// ---------------------------------------------------------------------------
// launcher
// ---------------------------------------------------------------------------
extern "C" void kernel_launch(void* const* d_in, const int* in_sizes, int n_in,
                              void* d_out, int out_size)
{
    (void)in_sizes; (void)n_in; (void)out_size;
    const void*  X   = d_in[0];
    const float* E   = (const float*)d_in[1];
    const float* Ww  = (const float*)d_in[2];
    const float* Wb  = (const float*)d_in[3];
    float*       out = (float*)d_out;

    cudaFuncSetAttribute(lstm_kernel,
                         cudaFuncAttributeMaxDynamicSharedMemorySize,
                         SMEM_TOTAL);

    split_kernel<<<8192, 256>>>(E, Ww);
    table_kernel<<<dim3(VOC / 64, G3 / 64), 256>>>(Wb);
    lstm_kernel<<<128, NT, SMEM_TOTAL>>>(X, Ww, out);
}